// round 5
// baseline (speedup 1.0000x reference)
#include <cuda_runtime.h>
#include <math.h>

#define NM 1024
#define HH 256
#define WW 256
#define HW 65536
#define OUT_MASKS ((size_t)NM * HW)            // 67108864 floats
#define OUT_KEEP_OFF OUT_MASKS                 // keep[1024]
#define OUT_BOX_OFF (OUT_MASKS + NM)           // boxes[1024*4]

#define IOU_THRESH 0.88f

// ---- scratch (no allocations allowed) ----
__device__ int   g_hi[NM];
__device__ int   g_lo[NM];
__device__ int   g_minr[NM];
__device__ int   g_maxr[NM];
__device__ int   g_minc[NM];
__device__ int   g_maxc[NM];
__device__ float g_gated[NM];
__device__ int   g_flag;               // NMS-done flag (reset each launch by kernel A)

// ============================================================
// Kernel A (fused): per-mask stats + zero-fill of output tiles
// for masks failing the iou threshold. Also resets g_flag.
//   blocks [0, NM)            : stats, one block per mask
//   blocks [NM, NM + 4*NM)    : zero-fill quarter-mask tiles
// ============================================================
__global__ void __launch_bounds__(256) sam_fused_kernel(const float* __restrict__ logits,
                                                        const float* __restrict__ iou_preds,
                                                        float* __restrict__ out)
{
    const int tid = threadIdx.x;

    if (blockIdx.x >= NM) {
        // ---- zero-fill path ----
        const int b = blockIdx.x - NM;
        if (b == 0 && tid == 0) g_flag = 0;      // reset handshake for kernel B
        const int n = b >> 2;
        const int q = b & 3;
        if (iou_preds[n] > IOU_THRESH) return;   // handled by kernel B
        float4* __restrict__ o4 = reinterpret_cast<float4*>(out)
                                + (size_t)n * (HW / 4) + (size_t)q * (HW / 16);
        const float4 z = make_float4(0.0f, 0.0f, 0.0f, 0.0f);
#pragma unroll
        for (int it = 0; it < 16; ++it)
            __stcs(&o4[it * 256 + tid], z);
        return;
    }

    // ---- stats path ----
    const int n = blockIdx.x;
    const float4* __restrict__ p =
        reinterpret_cast<const float4*>(logits + (size_t)n * HW);

    int hi = 0, lo = 0;
    int minr = HH, maxr = -1, minc = WW, maxc = -1;

    // 65536 elems = 16384 float4; 256 threads -> 64 iters
#pragma unroll 8
    for (int it = 0; it < 64; ++it) {
        const int i4 = it * 256 + tid;
        const float4 v = __ldcs(&p[i4]);
        const int e   = i4 << 2;
        const int row = e >> 8;
        const int col = e & 255;

        const float vs0 = v.x, vs1 = v.y, vs2 = v.z, vs3 = v.w;
        hi += (vs0 > 1.0f) + (vs1 > 1.0f) + (vs2 > 1.0f) + (vs3 > 1.0f);
        lo += (vs0 > -1.0f) + (vs1 > -1.0f) + (vs2 > -1.0f) + (vs3 > -1.0f);

        const bool b0 = vs0 > 0.0f, b1 = vs1 > 0.0f, b2 = vs2 > 0.0f, b3 = vs3 > 0.0f;
        if (b0 | b1 | b2 | b3) {
            minr = min(minr, row);
            maxr = max(maxr, row);
            if (b0) { minc = min(minc, col);     maxc = max(maxc, col);     }
            if (b1) { minc = min(minc, col + 1); maxc = max(maxc, col + 1); }
            if (b2) { minc = min(minc, col + 2); maxc = max(maxc, col + 2); }
            if (b3) { minc = min(minc, col + 3); maxc = max(maxc, col + 3); }
        }
    }

    // warp reduce
#pragma unroll
    for (int o = 16; o > 0; o >>= 1) {
        hi   += __shfl_down_sync(0xFFFFFFFFu, hi, o);
        lo   += __shfl_down_sync(0xFFFFFFFFu, lo, o);
        minr = min(minr, __shfl_down_sync(0xFFFFFFFFu, minr, o));
        maxr = max(maxr, __shfl_down_sync(0xFFFFFFFFu, maxr, o));
        minc = min(minc, __shfl_down_sync(0xFFFFFFFFu, minc, o));
        maxc = max(maxc, __shfl_down_sync(0xFFFFFFFFu, maxc, o));
    }

    __shared__ int s_hi[8], s_lo[8], s_minr[8], s_maxr[8], s_minc[8], s_maxc[8];
    const int w = tid >> 5;
    if ((tid & 31) == 0) {
        s_hi[w] = hi; s_lo[w] = lo;
        s_minr[w] = minr; s_maxr[w] = maxr;
        s_minc[w] = minc; s_maxc[w] = maxc;
    }
    __syncthreads();
    if (tid == 0) {
#pragma unroll
        for (int k = 1; k < 8; ++k) {
            hi += s_hi[k]; lo += s_lo[k];
            minr = min(minr, s_minr[k]); maxr = max(maxr, s_maxr[k]);
            minc = min(minc, s_minc[k]); maxc = max(maxc, s_maxc[k]);
        }
        g_hi[n] = hi;   g_lo[n] = lo;
        g_minr[n] = minr; g_maxr[n] = maxr;
        g_minc[n] = minc; g_maxc[n] = maxc;
    }
}

// ============================================================
// Kernel B: block 0 = NMS (stability filter + compaction +
// rank + greedy NMS, publishes g_gated then sets g_flag).
// Blocks 1..NM = output for one mask each:
//   iou-fail -> instant exit (already zeroed),
//   iou-pass -> spin for flag, then zero or sigmoid*g.
// ============================================================
__global__ void __launch_bounds__(1024) sam_nms_out_kernel(const float* __restrict__ logits,
                                                           const float* __restrict__ iou_preds,
                                                           float* __restrict__ out)
{
    const int j = threadIdx.x;

    if (blockIdx.x != 0) {
        // ---------------- worker block: one mask ----------------
        const int n = blockIdx.x - 1;
        if (iou_preds[n] <= IOU_THRESH) return;   // tile already zeroed by kernel A

        // wait for NMS result
        if (j == 0) {
            while (atomicAdd(&g_flag, 0) == 0) __nanosleep(64);
        }
        __syncthreads();
        __threadfence();                           // acquire g_gated written by block 0

        const float g = g_gated[n];
        const size_t base4 = (size_t)n * (HW / 4);
        const float4* __restrict__ in4 = reinterpret_cast<const float4*>(logits) + base4;
        float4* __restrict__ o4 = reinterpret_cast<float4*>(out) + base4;

        if (g == 0.0f) {
            const float4 z = make_float4(0.0f, 0.0f, 0.0f, 0.0f);
#pragma unroll
            for (int it = 0; it < 16; ++it)
                __stcs(&o4[it * 1024 + j], z);
        } else {
#pragma unroll 4
            for (int it = 0; it < 16; ++it) {
                float4 v = __ldcs(&in4[it * 1024 + j]);
                v.x = g / (1.0f + __expf(-v.x));
                v.y = g / (1.0f + __expf(-v.y));
                v.z = g / (1.0f + __expf(-v.z));
                v.w = g / (1.0f + __expf(-v.w));
                __stcs(&o4[it * 1024 + j], v);
            }
        }
        return;
    }

    // ---------------- block 0: NMS ----------------
    const int wid = j >> 5;
    const unsigned lane_lt = (1u << (j & 31)) - 1u;

    __shared__ int   s_wcnt[32];
    __shared__ float s_ckey[NM];     // compact keys (scores of valid)
    __shared__ int   s_cidx[NM];     // compact original indices
    __shared__ float s_sl[NM], s_st[NM], s_sr[NM], s_sb[NM];  // sorted boxes
    __shared__ unsigned char s_keep[NM];

    const float score = iou_preds[j];
    const float hi = (float)g_hi[j];
    const float lo = (float)g_lo[j];
    const float stability = hi / fmaxf(lo, 1.0f);

    const int minr = g_minr[j], maxr = g_maxr[j];
    const int minc = g_minc[j], maxc = g_maxc[j];
    const bool empty = (maxr < 0);
    const float bl = empty ? 0.0f : (float)minc;
    const float bt = empty ? 0.0f : (float)minr;
    const float br = empty ? 0.0f : (float)maxc;
    const float bb = empty ? 0.0f : (float)maxr;

    const bool valid = (score > IOU_THRESH) && (stability >= 0.95f);

    // ---- stable compaction of valid entries ----
    const unsigned ballot = __ballot_sync(0xFFFFFFFFu, valid);
    if ((j & 31) == 0) s_wcnt[wid] = __popc(ballot);
    __syncthreads();

    int warp_off = 0, nvalid = 0;
#pragma unroll
    for (int k = 0; k < 32; ++k) {
        const int c = s_wcnt[k];
        if (k < wid) warp_off += c;
        nvalid += c;
    }
    const int cpos = warp_off + __popc(ballot & lane_lt);

    if (valid) {
        s_ckey[cpos] = score;
        s_cidx[cpos] = j;
    }
    __syncthreads();

    // ---- stable descending rank among valid entries only ----
    int rank = 0;
    if (valid) {
        for (int i = 0; i < nvalid; ++i) {
            const float kk = s_ckey[i];
            rank += (kk > score) || ((kk == score) && (s_cidx[i] < j));
        }
        s_sl[rank] = bl; s_st[rank] = bt; s_sr[rank] = br; s_sb[rank] = bb;
        s_keep[rank] = 1;
    }
    __syncthreads();

    // ---- greedy NMS over sorted valid entries ----
    float tl = 0.f, tt = 0.f, tr = 0.f, tb = 0.f, myArea = 0.f;
    if (j < nvalid) {
        tl = s_sl[j]; tt = s_st[j]; tr = s_sr[j]; tb = s_sb[j];
        myArea = fmaxf(tr - tl, 0.0f) * fmaxf(tb - tt, 0.0f);
    }

    for (int i = 0; i < nvalid; ++i) {
        __syncthreads();
        if (!s_keep[i]) continue;           // uniform branch (shared value)
        if (j > i && j < nvalid && s_keep[j]) {
            const float il = s_sl[i], it_ = s_st[i], ir = s_sr[i], ib = s_sb[i];
            const float x0 = fmaxf(il, tl), y0 = fmaxf(it_, tt);
            const float x1 = fminf(ir, tr), y1 = fminf(ib, tb);
            const float inter = fmaxf(x1 - x0, 0.0f) * fmaxf(y1 - y0, 0.0f);
            const float areaI = fmaxf(ir - il, 0.0f) * fmaxf(ib - it_, 0.0f);
            const float uni = fmaxf(areaI + myArea - inter, 1e-6f);
            if (inter / uni > 0.7f) s_keep[j] = 0;
        }
    }
    __syncthreads();

    const bool kept = valid && (s_keep[rank] != 0);
    g_gated[j] = kept ? score : 0.0f;

    out[OUT_KEEP_OFF + j] = kept ? 1.0f : 0.0f;
    float* ob = out + OUT_BOX_OFF + (size_t)j * 4;
    ob[0] = bl; ob[1] = bt; ob[2] = br; ob[3] = bb;

    // publish: make g_gated globally visible, then raise flag
    __syncthreads();
    __threadfence();
    if (j == 0) atomicExch(&g_flag, 1);
}

extern "C" void kernel_launch(void* const* d_in, const int* in_sizes, int n_in,
                              void* d_out, int out_size)
{
    const float* logits    = (const float*)d_in[0];  // [1024,256,256]
    const float* iou_preds = (const float*)d_in[1];  // [1024]
    float* out = (float*)d_out;

    sam_fused_kernel<<<NM + NM * 4, 256>>>(logits, iou_preds, out);
    sam_nms_out_kernel<<<1 + NM, 1024>>>(logits, iou_preds, out);
}

// round 6
// speedup vs baseline: 1.0456x; 1.0456x over previous
#include <cuda_runtime.h>
#include <math.h>

#define NM 1024
#define HH 256
#define WW 256
#define HW 65536
#define OUT_MASKS ((size_t)NM * HW)            // 67108864 floats
#define OUT_KEEP_OFF OUT_MASKS                 // keep[1024]
#define OUT_BOX_OFF (OUT_MASKS + NM)           // boxes[1024*4]

#define IOU_THRESH 0.88f

// ---- scratch (no allocations allowed) ----
__device__ int   g_hi[NM];
__device__ int   g_lo[NM];
__device__ int   g_minr[NM];
__device__ int   g_maxr[NM];
__device__ int   g_minc[NM];
__device__ int   g_maxc[NM];
__device__ float g_gated[NM];
__device__ int   g_done;               // stats-blocks-finished counter (self-resetting)

// ============================================================
// Kernel A: stats (1 block/mask) + zero-fill for iou-fail masks
// + last-stats-block runs the full filter/sort/NMS tail.
//   blocks [0, NM)          : stats
//   blocks [NM, NM + 4*NM)  : zero-fill quarter tiles
// ============================================================
__global__ void __launch_bounds__(256) sam_stats_nms_kernel(const float* __restrict__ logits,
                                                            const float* __restrict__ iou_preds,
                                                            float* __restrict__ out)
{
    const int tid = threadIdx.x;

    if (blockIdx.x >= NM) {
        // ---- zero-fill path (iou-fail masks only) ----
        const int b = blockIdx.x - NM;
        const int n = b >> 2;
        const int q = b & 3;
        if (iou_preds[n] > IOU_THRESH) return;   // handled by kernel B
        float4* __restrict__ o4 = reinterpret_cast<float4*>(out)
                                + (size_t)n * (HW / 4) + (size_t)q * (HW / 16);
        const float4 z = make_float4(0.0f, 0.0f, 0.0f, 0.0f);
#pragma unroll
        for (int it = 0; it < 16; ++it)
            __stcs(&o4[it * 256 + tid], z);
        return;
    }

    // ================= stats path =================
    const int n = blockIdx.x;
    const float4* __restrict__ p =
        reinterpret_cast<const float4*>(logits + (size_t)n * HW);

    int hi = 0, lo = 0;
    int minr = HH, maxr = -1, minc = WW, maxc = -1;

#pragma unroll 8
    for (int it = 0; it < 64; ++it) {
        const int i4 = it * 256 + tid;
        const float4 v = __ldcs(&p[i4]);
        const int e   = i4 << 2;
        const int row = e >> 8;
        const int col = e & 255;

        const float vs0 = v.x, vs1 = v.y, vs2 = v.z, vs3 = v.w;
        hi += (vs0 > 1.0f) + (vs1 > 1.0f) + (vs2 > 1.0f) + (vs3 > 1.0f);
        lo += (vs0 > -1.0f) + (vs1 > -1.0f) + (vs2 > -1.0f) + (vs3 > -1.0f);

        const bool b0 = vs0 > 0.0f, b1 = vs1 > 0.0f, b2 = vs2 > 0.0f, b3 = vs3 > 0.0f;
        if (b0 | b1 | b2 | b3) {
            minr = min(minr, row);
            maxr = max(maxr, row);
            if (b0) { minc = min(minc, col);     maxc = max(maxc, col);     }
            if (b1) { minc = min(minc, col + 1); maxc = max(maxc, col + 1); }
            if (b2) { minc = min(minc, col + 2); maxc = max(maxc, col + 2); }
            if (b3) { minc = min(minc, col + 3); maxc = max(maxc, col + 3); }
        }
    }

#pragma unroll
    for (int o = 16; o > 0; o >>= 1) {
        hi   += __shfl_down_sync(0xFFFFFFFFu, hi, o);
        lo   += __shfl_down_sync(0xFFFFFFFFu, lo, o);
        minr = min(minr, __shfl_down_sync(0xFFFFFFFFu, minr, o));
        maxr = max(maxr, __shfl_down_sync(0xFFFFFFFFu, maxr, o));
        minc = min(minc, __shfl_down_sync(0xFFFFFFFFu, minc, o));
        maxc = max(maxc, __shfl_down_sync(0xFFFFFFFFu, maxc, o));
    }

    __shared__ int s_hi[8], s_lo[8], s_minr[8], s_maxr[8], s_minc[8], s_maxc[8];
    const int w = tid >> 5;
    if ((tid & 31) == 0) {
        s_hi[w] = hi; s_lo[w] = lo;
        s_minr[w] = minr; s_maxr[w] = maxr;
        s_minc[w] = minc; s_maxc[w] = maxc;
    }
    __syncthreads();

    __shared__ int s_last;
    if (tid == 0) {
#pragma unroll
        for (int k = 1; k < 8; ++k) {
            hi += s_hi[k]; lo += s_lo[k];
            minr = min(minr, s_minr[k]); maxr = max(maxr, s_maxr[k]);
            minc = min(minc, s_minc[k]); maxc = max(maxc, s_maxc[k]);
        }
        g_hi[n] = hi;   g_lo[n] = lo;
        g_minr[n] = minr; g_maxr[n] = maxr;
        g_minc[n] = minc; g_maxc[n] = maxc;

        // this block's box (depends only on own stats)
        const bool empty = (maxr < 0);
        float* ob = out + OUT_BOX_OFF + (size_t)n * 4;
        ob[0] = empty ? 0.0f : (float)minc;
        ob[1] = empty ? 0.0f : (float)minr;
        ob[2] = empty ? 0.0f : (float)maxc;
        ob[3] = empty ? 0.0f : (float)maxr;

        __threadfence();
        s_last = (atomicAdd(&g_done, 1) == NM - 1);
    }
    __syncthreads();
    if (!s_last) return;

    // ================= NMS tail (one block, 256 threads) =================
    __shared__ float s_ckey[NM];     // compact: score
    __shared__ int   s_cidx[NM];     // compact: original index
    __shared__ float s_sl[NM], s_st[NM], s_sr[NM], s_sb[NM];  // sorted boxes
    __shared__ int   s_sidx[NM];     // sorted: original index
    __shared__ float s_sscore[NM];   // sorted: score
    __shared__ unsigned char s_keep[NM];
    __shared__ int   s_nv;

    if (tid == 0) s_nv = 0;
    __syncthreads();

    // each thread handles 4 masks; gather validity, compact (order-agnostic)
    float my_sc[4], my_bl[4], my_bt[4], my_br[4], my_bb[4];
    int   my_m[4], my_pos[4];
    bool  my_valid[4];
#pragma unroll
    for (int k = 0; k < 4; ++k) {
        const int m = tid + k * 256;
        my_m[k] = m;
        const float sc = iou_preds[m];
        const float fhi = (float)g_hi[m];
        const float flo = (float)g_lo[m];
        const float stability = fhi / fmaxf(flo, 1.0f);
        const int mr0 = g_minr[m], mr1 = g_maxr[m];
        const int mc0 = g_minc[m], mc1 = g_maxc[m];
        const bool empty = (mr1 < 0);
        my_sc[k] = sc;
        my_bl[k] = empty ? 0.0f : (float)mc0;
        my_bt[k] = empty ? 0.0f : (float)mr0;
        my_br[k] = empty ? 0.0f : (float)mc1;
        my_bb[k] = empty ? 0.0f : (float)mr1;
        my_valid[k] = (sc > IOU_THRESH) && (stability >= 0.95f);
        if (my_valid[k]) {
            const int pos = atomicAdd(&s_nv, 1);
            my_pos[k] = pos;
            s_ckey[pos] = sc;
            s_cidx[pos] = m;
        }
    }
    __syncthreads();
    const int nvalid = s_nv;

    // stable descending rank (score desc, orig idx asc) + scatter
#pragma unroll
    for (int k = 0; k < 4; ++k) {
        if (!my_valid[k]) continue;
        const float sc = my_sc[k];
        const int   m  = my_m[k];
        int rank = 0;
        for (int i = 0; i < nvalid; ++i) {
            const float kk = s_ckey[i];
            rank += (kk > sc) || ((kk == sc) && (s_cidx[i] < m));
        }
        s_sl[rank] = my_bl[k]; s_st[rank] = my_bt[k];
        s_sr[rank] = my_br[k]; s_sb[rank] = my_bb[k];
        s_sidx[rank] = m; s_sscore[rank] = sc;
        (void)my_pos[k];
    }
    __syncthreads();

    // warp 0: greedy NMS, no block barriers
    if (tid < 32) {
        const int lane = tid;
        unsigned alive = 0;
#pragma unroll
        for (int t = 0; t < 32; ++t)
            if (lane + (t << 5) < nvalid) alive |= (1u << t);

        for (int i = 0; i < nvalid; ++i) {
            const int ol = i & 31, obit = i >> 5;
            const unsigned oa = __shfl_sync(0xFFFFFFFFu, alive, ol);
            if (!((oa >> obit) & 1)) continue;           // warp-uniform
            const float il = s_sl[i], it_ = s_st[i], ir = s_sr[i], ib = s_sb[i];
            const float areaI = fmaxf(ir - il, 0.0f) * fmaxf(ib - it_, 0.0f);
            const int d = i - lane;
            const int tmin = (d < 0) ? 0 : ((d >> 5) + 1);
            unsigned mset = (tmin >= 32) ? 0u : (alive & (0xFFFFFFFFu << tmin));
            while (mset) {
                const int t = __ffs(mset) - 1; mset &= mset - 1;
                const int jj = lane + (t << 5);
                const float tl = s_sl[jj], tt = s_st[jj], tr = s_sr[jj], tb = s_sb[jj];
                const float x0 = fmaxf(il, tl), y0 = fmaxf(it_, tt);
                const float x1 = fminf(ir, tr), y1 = fminf(ib, tb);
                const float inter = fmaxf(x1 - x0, 0.0f) * fmaxf(y1 - y0, 0.0f);
                const float areaJ = fmaxf(tr - tl, 0.0f) * fmaxf(tb - tt, 0.0f);
                if (inter / fmaxf(areaI + areaJ - inter, 1e-6f) > 0.7f)
                    alive &= ~(1u << t);
            }
        }
#pragma unroll
        for (int t = 0; t < 32; ++t) {
            const int jj = lane + (t << 5);
            if (jj < nvalid) s_keep[jj] = (alive >> t) & 1;
        }
    }
    __syncthreads();

    // defaults, then kept overrides
#pragma unroll
    for (int k = 0; k < 4; ++k) {
        const int m = tid + k * 256;
        g_gated[m] = 0.0f;
        out[OUT_KEEP_OFF + m] = 0.0f;
    }
    __syncthreads();
    for (int s = tid; s < nvalid; s += 256) {
        if (s_keep[s]) {
            const int m = s_sidx[s];
            g_gated[m] = s_sscore[s];
            out[OUT_KEEP_OFF + m] = 1.0f;
        }
    }

    __syncthreads();
    if (tid == 0) g_done = 0;   // reset for next graph replay
}

// ============================================================
// Kernel B: output for iou-pass masks only (rest already zeroed).
// ============================================================
__global__ void __launch_bounds__(256) sam_out_kernel(const float* __restrict__ logits,
                                                      const float* __restrict__ iou_preds,
                                                      float* __restrict__ out)
{
    const int n = blockIdx.x >> 2;
    if (iou_preds[n] <= IOU_THRESH) return;
    const int q = blockIdx.x & 3;
    const float g = g_gated[n];

    const size_t base4 = (size_t)n * (HW / 4) + (size_t)q * (HW / 16);
    const float4* __restrict__ in4 = reinterpret_cast<const float4*>(logits) + base4;
    float4* __restrict__ o4 = reinterpret_cast<float4*>(out) + base4;
    const int tid = threadIdx.x;

    if (g == 0.0f) {
        const float4 z = make_float4(0.0f, 0.0f, 0.0f, 0.0f);
#pragma unroll
        for (int it = 0; it < 16; ++it)
            __stcs(&o4[it * 256 + tid], z);
    } else {
#pragma unroll 4
        for (int it = 0; it < 16; ++it) {
            float4 v = __ldcs(&in4[it * 256 + tid]);
            v.x = g / (1.0f + __expf(-v.x));
            v.y = g / (1.0f + __expf(-v.y));
            v.z = g / (1.0f + __expf(-v.z));
            v.w = g / (1.0f + __expf(-v.w));
            __stcs(&o4[it * 256 + tid], v);
        }
    }
}

extern "C" void kernel_launch(void* const* d_in, const int* in_sizes, int n_in,
                              void* d_out, int out_size)
{
    const float* logits    = (const float*)d_in[0];  // [1024,256,256]
    const float* iou_preds = (const float*)d_in[1];  // [1024]
    float* out = (float*)d_out;

    sam_stats_nms_kernel<<<NM + NM * 4, 256>>>(logits, iou_preds, out);
    sam_out_kernel<<<NM * 4, 256>>>(logits, iou_preds, out);
}